// round 15
// baseline (speedup 1.0000x reference)
#include <cuda_runtime.h>
#include <cstddef>

// Bidirectional CTC batch cost, prob-domain, exact power-of-two renorm,
// single fused kernel with atomic rendezvous join.
// 1024 single-warp CTAs; unit u = (batch b = u>>1, dir = u&1).
//   dir 0: forward alpha over t=0..255. dir 1: identical recurrence on the
//   time+state-reversed lattice over t=511..256 (labels reversed).
//   Each warp streams its 32 chunks (4KB rows) via cp.async into a 5-slot
//   smem ring; publishes final 129 alphas + scale exponent K to global
//   scratch; the LAST of each batch's two units to arrive (atomicAdd
//   rendezvous, no spinning) performs the double-precision junction:
//     L = sum_s Ab[128-s] * (Af[s] + Af[s-1] + skip[s]*Af[s-2])
//   and resets the counter (replay-clean for CUDA graphs).
// B=512, T=512, C=128, L=64, S=129.

#define CTC_B 512
#define CTC_T 512
#define CTC_C 128
#define CTC_L 64
#define CHUNK 8                     // steps per chunk == renorm period
#define HCHUNK 32                   // chunks per direction (32*8 = 256 steps)
#define SLOTS 5                     // ring slots
#define DIST 4                      // chunk-groups in flight
#define NUNITS (2 * CTC_B)          // 1024 half-streams

__device__ float g_alpha[NUNITS][CTC_C + 4];   // [u][0..128] final alphas
__device__ int   g_K[NUNITS];                  // [u] accumulated log2 scale
__device__ int   g_count[CTC_B];               // rendezvous counters (start 0)

__global__ __launch_bounds__(32)
void ctc_half_kernel(const int* __restrict__ y_true,
                     const float* __restrict__ y_pred,
                     float* __restrict__ out)
{
    __shared__ float ring[SLOTS * CHUNK * CTC_C];   // 20 KB

    const int u    = blockIdx.x;
    const int b    = u >> 1;
    const int dir  = u & 1;               // 0 = forward, 1 = backward
    const int lane = threadIdx.x;
    const unsigned FULL = 0xffffffffu;
    const float EPSF = 1e-7f;

    // Labels owned by this lane. Forward: states 4l+1 -> y[2l], 4l+3 -> y[2l+1].
    // Backward (reversed ext): sigma=4l+1 -> y[63-2l], sigma=4l+3 -> y[62-2l].
    const int i0 = dir ? (63 - 2 * lane) : (2 * lane);
    const int i1 = dir ? (62 - 2 * lane) : (2 * lane + 1);
    const int c0 = y_true[b * CTC_L + i0];
    const int c1 = y_true[b * CTC_L + i1];
    const int c1_prev = __shfl_up_sync(FULL, c1, 1);
    const bool skip1 = (lane > 0) && (c0 != c1_prev);
    const bool skip3 = (c1 != c0);

    const float* row0 = y_pred + (size_t)b * CTC_T * CTC_C;

    // cp.async one full row (512B) coalesced: lane takes 16B at offset lane*16.
    const unsigned ring_base = (unsigned)__cvta_generic_to_shared(ring);
    auto load_chunk = [&](int c) {   // direction-local chunk c -> slot c%SLOTS
        if (c < HCHUNK) {
            const int g = dir ? (63 - c) : c;         // global chunk index
            const int sbase = (c % SLOTS) * CHUNK;
            #pragma unroll
            for (int j = 0; j < CHUNK; ++j) {
                unsigned dst = ring_base + (unsigned)(((sbase + j) * CTC_C + lane * 4) * 4);
                const float* src = row0 + (size_t)(g * CHUNK + j) * CTC_C + lane * 4;
                asm volatile("cp.async.cg.shared.global [%0], [%1], 16;\n"
                             :: "r"(dst), "l"(src));
            }
        }
        asm volatile("cp.async.commit_group;\n" ::: "memory");  // commit even if empty
    };

    for (int c = 0; c < DIST; ++c) load_chunk(c);

    // Virtual alpha_{-1} = (2^100, 0, 0, ...) at lane 0; true alpha = stored * 2^K.
    const float TWO100 = __int_as_float((100 + 127) << 23);  // 2^100
    float a0 = (lane == 0) ? TWO100 : 0.0f;
    float a1 = 0.0f, a2 = 0.0f, a3 = 0.0f, a4 = 0.0f;
    float pm1 = 0.0f;     // alpha_{t-1}[4l-1] (prev lane's a3), pipelined shfl
    int   K   = -100;     // integer log2 of the accumulated scale

    for (int c = 0; c < HCHUNK; ++c) {
        load_chunk(c + DIST);
        asm volatile("cp.async.wait_group %0;\n" :: "n"(DIST) : "memory");
        __syncwarp();

        const int sbase = (c % SLOTS) * CHUNK;
        #pragma unroll
        for (int j = 0; j < CHUNK; ++j) {
            const int jr = dir ? (CHUNK - 1 - j) : j;   // bwd consumes rows reversed
            const float* rs = &ring[(sbase + jr) * CTC_C];
            const float pb = rs[CTC_C - 1] + EPSF;  // blank (broadcast LDS)
            const float p0 = rs[c0] + EPSF;         // scattered LDS
            const float p1 = rs[c1] + EPSF;

            // new[s] = p[s] * (a[s] + a[s-1] + skip*a[s-2]); states 4l..4l+3 (+128)
            const float n3 = p1 * ((a2 + (skip3 ? a1 : 0.0f)) + a3);
            const float n2 = pb * (a1 + a2);
            const float sh = __shfl_up_sync(FULL, n3, 1);
            const float n0 = pb * (a0 + pm1);
            const float n1 = p0 * ((a0 + (skip1 ? pm1 : 0.0f)) + a1);
            const float n4 = (lane == 31) ? pb * (a3 + a4) : 0.0f;

            pm1 = (lane == 0) ? 0.0f : sh;
            a0 = n0; a1 = n1; a2 = n2; a3 = n3; a4 = n4;
        }

        // Exact renorm: warp max (redux on bits — order-preserving for >=0),
        // round down to 2^k, rescale so max sits in [2^100, 2^101). Scale is an
        // exact power of two tracked in integer K (zero rounding added).
        float m = fmaxf(fmaxf(fmaxf(a0, a1), fmaxf(a2, a3)), a4);
        m = __uint_as_float(__reduce_max_sync(FULL, __float_as_uint(m)));
        const int k = (int)((__float_as_uint(m) >> 23) & 0xff) - 127;
        K += k - 100;
        const float s1 = __int_as_float((127 - k) << 23);  // 2^-k (exact)
        a0 = a0 * s1 * TWO100;
        a1 = a1 * s1 * TWO100;
        a2 = a2 * s1 * TWO100;
        a3 = a3 * s1 * TWO100;
        a4 = a4 * s1 * TWO100;
        pm1 = pm1 * s1 * TWO100;
    }

    // Publish final alphas in this direction's own state coordinates.
    {
        float* ga = g_alpha[u];
        const int s0 = 4 * lane;
        ga[s0]     = a0;
        ga[s0 + 1] = a1;
        ga[s0 + 2] = a2;
        ga[s0 + 3] = a3;
        if (lane == 31) { ga[128] = a4; g_K[u] = K; }
    }

    // ── Rendezvous: the LAST unit of this batch to arrive performs the join.
    __threadfence();                                   // release our alphas
    int old = 0;
    if (lane == 0) old = atomicAdd(&g_count[b], 1);
    old = __shfl_sync(FULL, old, 0);
    if (old != 1) return;                              // first arrival: done

    __threadfence();                                   // acquire peer's alphas

    // Forward-orientation skip flags (recomputed; we may be the bwd unit).
    const int f0 = y_true[b * CTC_L + 2 * lane];
    const int f1 = y_true[b * CTC_L + 2 * lane + 1];
    const int f1_prev = __shfl_up_sync(FULL, f1, 1);
    const bool fskip1 = (lane > 0) && (f0 != f1_prev);
    const bool fskip3 = (f1 != f0);

    const float* Af = g_alpha[2 * b];       // forward alphas, state s
    const float* Ab = g_alpha[2 * b + 1];   // backward alphas, sigma = 128 - s

    const int s = 4 * lane;
    const double A0 = Af[s],     A1 = Af[s + 1];
    const double A2 = Af[s + 2], A3 = Af[s + 3];
    const double Am1 = (lane > 0) ? (double)Af[s - 1] : 0.0;

    // Atilde(s) = A[s] + A[s-1] + skip[s]*A[s-2]; betaP(s) = Ab[128-s].
    const double At0 = A0 + Am1;
    const double At1 = (A1 + A0) + (fskip1 ? Am1 : 0.0);
    const double At2 = A2 + A1;
    const double At3 = (A3 + A2) + (fskip3 ? A1 : 0.0);

    double t = At0 * (double)Ab[128 - s]
             + At1 * (double)Ab[127 - s]
             + At2 * (double)Ab[126 - s]
             + At3 * (double)Ab[125 - s];
    if (lane == 31) {
        // s = 128 (last blank): Atilde = A[128] + A[127] (no skip into blank).
        t += ((double)Af[128] + (double)Af[127]) * (double)Ab[0];
    }

    #pragma unroll
    for (int o = 16; o; o >>= 1) t += __shfl_xor_sync(FULL, t, o);

    if (lane == 0) {
        const int Ksum = g_K[2 * b] + g_K[2 * b + 1];
        out[b] = (float)(-(log(t) + (double)Ksum * 0.6931471805599453));
        g_count[b] = 0;   // reset for next CUDA-graph replay (deterministic)
    }
}

extern "C" void kernel_launch(void* const* d_in, const int* in_sizes, int n_in,
                              void* d_out, int out_size)
{
    // Resolve inputs by size (y_true: 512*64 int32, y_pred: 512*512*128 float32).
    const void* p0 = d_in[0];
    const void* p1 = d_in[1];
    const int* y_true;
    const float* y_pred;
    if (in_sizes[0] == CTC_B * CTC_L) {
        y_true = (const int*)p0;
        y_pred = (const float*)p1;
    } else {
        y_true = (const int*)p1;
        y_pred = (const float*)p0;
    }
    float* out = (float*)d_out;

    ctc_half_kernel<<<NUNITS, 32>>>(y_true, y_pred, out);
}

// round 16
// speedup vs baseline: 1.0701x; 1.0701x over previous
#include <cuda_runtime.h>
#include <cstddef>

// CTC batch cost, prob-domain forward with exact power-of-two renormalization.
// 512 CTAs x 64 threads. Warp 0 = R5's proven consumer: lane l owns lattice
// states 4l..4l+3 (lane 31 also 128); streams rows into an 8-slot cp.async
// ring (DIST=7) and runs the recurrence. Warp 1 = L2 warmer: free-runs
// ld.global.cg over the same rows up to LEAD chunks ahead of consumption
// (volatile smem progress counter; no barriers -> no deadlock possible),
// converting the consumer's cp.async fills into L2 hits and decoupling DRAM
// request generation from the ring's latency feedback loop.
// B=512, T=512, C=128, L=64, S=129.

#define CTC_B 512
#define CTC_T 512
#define CTC_C 128
#define CTC_L 64
#define CHUNK 8                    // steps per chunk == renorm period
#define NCHUNK (CTC_T / CHUNK)     // 64
#define DIST 7                     // cp.async chunk-groups kept in flight
#define SLOTS 8                    // ring slots (DIST+1 decouples refill/consume)
#define LEAD 16                    // warmer lead bound, in chunks (64 KB window)

__global__ __launch_bounds__(64)
void ctc_warp_kernel(const int* __restrict__ y_true,
                     const float* __restrict__ y_pred,
                     float* __restrict__ out)
{
    __shared__ float ring[SLOTS * CHUNK * CTC_C];   // 32 KB
    __shared__ volatile int prog;                   // chunks consumed so far

    const int b    = blockIdx.x;
    const int tid  = threadIdx.x;
    const int lane = tid & 31;
    const int wid  = tid >> 5;            // 0 = consumer, 1 = L2 warmer
    const unsigned FULL = 0xffffffffu;
    const float EPSF = 1e-7f;

    const float* row0 = y_pred + (size_t)b * CTC_T * CTC_C;

    if (tid == 0) prog = 0;
    __syncthreads();

    if (wid == 1) {
        // ───────── L2 warmer: free-running bounded prefetch ─────────
        // For each chunk, 8 x ld.global.cg.v4 (512B/instr, L1-bypassed,
        // fills L2). asm volatile keeps the dead loads. Bounded LEAD chunks
        // ahead of the consumer's consumption point; never blocks anyone.
        for (int c = DIST; c < NCHUNK; ++c) {
            while (c > prog + LEAD) __nanosleep(64);
            const float* src = row0 + (size_t)c * CHUNK * CTC_C + lane * 4;
            #pragma unroll
            for (int j = 0; j < CHUNK; ++j) {
                unsigned d0, d1, d2, d3;
                asm volatile("ld.global.cg.v4.b32 {%0,%1,%2,%3}, [%4];"
                             : "=r"(d0), "=r"(d1), "=r"(d2), "=r"(d3)
                             : "l"(src + j * CTC_C));
            }
        }
        return;
    }

    // ───────── Consumer: R5 body, unchanged ─────────
    // Labels owned by this lane: k0 = 2*lane -> state 4l+1, k1 = 2*lane+1 -> state 4l+3
    const int c0 = y_true[b * CTC_L + 2 * lane];
    const int c1 = y_true[b * CTC_L + 2 * lane + 1];
    const int c1_prev = __shfl_up_sync(FULL, c1, 1);   // y[2l-1] lives in prev lane
    const bool skip1 = (lane > 0) && (c0 != c1_prev);  // state 4l+1: y[2l] != y[2l-1]
    const bool skip3 = (c1 != c0);                     // state 4l+3: y[2l+1] != y[2l]

    // cp.async one full row (512B) coalesced: lane takes 16B at offset lane*16.
    const unsigned ring_base = (unsigned)__cvta_generic_to_shared(ring);
    auto load_chunk = [&](int c) {   // rows c*CHUNK.. into ring slot c%SLOTS
        const int sbase = (c % SLOTS) * CHUNK;
        if (c < NCHUNK) {
            #pragma unroll
            for (int j = 0; j < CHUNK; ++j) {
                const int t = c * CHUNK + j;
                unsigned dst = ring_base + (unsigned)(((sbase + j) * CTC_C + lane * 4) * 4);
                const float* src = row0 + (size_t)t * CTC_C + lane * 4;
                asm volatile("cp.async.cg.shared.global [%0], [%1], 16;\n"
                             :: "r"(dst), "l"(src));
            }
        }
        asm volatile("cp.async.commit_group;\n" ::: "memory");  // commit even if empty
    };

    // Prologue: DIST chunk-groups in flight.
    for (int c = 0; c < DIST; ++c) load_chunk(c);

    // Virtual alpha_{-1} = (2^100, 0, 0, ...) at lane 0; true alpha = stored * 2^K.
    const float TWO100 = __int_as_float((100 + 127) << 23);  // 2^100
    float a0 = (lane == 0) ? TWO100 : 0.0f;
    float a1 = 0.0f, a2 = 0.0f, a3 = 0.0f, a4 = 0.0f;
    float pm1 = 0.0f;     // alpha_{t-1}[4l-1] (prev lane's a3), pipelined shfl
    int   K   = -100;     // integer log2 of the accumulated scale

    for (int c = 0; c < NCHUNK; ++c) {
        // Issue group c+DIST first (writes the slot consumed at iteration c-1,
        // whose LDS reads completed a full iteration ago) — keeps DIST groups
        // in flight through the compute phase.
        load_chunk(c + DIST);

        // Group c must be complete; up to DIST newer groups stay pending.
        asm volatile("cp.async.wait_group %0;\n" :: "n"(DIST) : "memory");
        __syncwarp();   // cross-lane visibility of cp.async-written smem

        // Publish consumption progress for the warmer warp.
        if (lane == 0) prog = c + 1;

        const int sbase = (c % SLOTS) * CHUNK;
        #pragma unroll
        for (int j = 0; j < CHUNK; ++j) {
            const float* rs = ring + (sbase + j) * CTC_C;
            const float pb = rs[CTC_C - 1] + EPSF;  // broadcast LDS
            const float p0 = rs[c0] + EPSF;         // scattered LDS
            const float p1 = rs[c1] + EPSF;

            // new[s] = p[s] * (a[s] + a[s-1] + skip*a[s-2]); states 4l..4l+3 (+128)
            const float n3 = p1 * ((a2 + (skip3 ? a1 : 0.0f)) + a3);   // s=4l+3 (label k1)
            const float n2 = pb * (a1 + a2);                           // s=4l+2 (blank)
            const float sh = __shfl_up_sync(FULL, n3, 1);              // next step's alpha[4l-1]
            const float n0 = pb * (a0 + pm1);                          // s=4l   (blank)
            const float n1 = p0 * ((a0 + (skip1 ? pm1 : 0.0f)) + a1);  // s=4l+1 (label k0)
            const float n4 = (lane == 31) ? pb * (a3 + a4) : 0.0f;     // s=128  (last blank)

            pm1 = (lane == 0) ? 0.0f : sh;
            a0 = n0; a1 = n1; a2 = n2; a3 = n3; a4 = n4;
        }

        // Exact renorm: warp max via redux (bits order-preserving for non-negative
        // floats), round down to 2^k, rescale so max sits in [2^100, 2^101).
        // Scale 2^(100-k) applied as two exact power-of-2 multiplies; K accumulates
        // the exact integer log2 of the total scale (zero rounding added).
        float m = fmaxf(fmaxf(fmaxf(a0, a1), fmaxf(a2, a3)), a4);
        m = __uint_as_float(__reduce_max_sync(FULL, __float_as_uint(m)));
        const int k = (int)((__float_as_uint(m) >> 23) & 0xff) - 127;  // floor(log2 m)
        K += k - 100;
        const float s1 = __int_as_float((127 - k) << 23);  // 2^-k   (exact)
        a0 = a0 * s1 * TWO100;
        a1 = a1 * s1 * TWO100;
        a2 = a2 * s1 * TWO100;
        a3 = a3 * s1 * TWO100;
        a4 = a4 * s1 * TWO100;
        pm1 = pm1 * s1 * TWO100;
    }

    // ll = log(alpha_T[S-2] + alpha_T[S-1]) + K*ln2 ; states 127,128 live in lane 31.
    if (lane == 31) {
        out[b] = -(logf(a3 + a4) + (float)K * 0.693147180559945309f);
    }
}

extern "C" void kernel_launch(void* const* d_in, const int* in_sizes, int n_in,
                              void* d_out, int out_size)
{
    // Resolve inputs by size (y_true: 512*64 int32, y_pred: 512*512*128 float32).
    const void* p0 = d_in[0];
    const void* p1 = d_in[1];
    const int* y_true;
    const float* y_pred;
    if (in_sizes[0] == CTC_B * CTC_L) {
        y_true = (const int*)p0;
        y_pred = (const float*)p1;
    } else {
        y_true = (const int*)p1;
        y_pred = (const float*)p0;
    }
    float* out = (float*)d_out;

    ctc_warp_kernel<<<CTC_B, 64>>>(y_true, y_pred, out);
}